// round 1
// baseline (speedup 1.0000x reference)
#include <cuda_runtime.h>
#include <math.h>

#define K_DIM 1024
#define N_DIM 16384
#define SCAN_C 256
#define SCAN_H 64

// Scratch (static device globals — no dynamic allocation allowed)
__device__ float  g_G[(size_t)N_DIM * K_DIM];   // G[t][k] = Beta[k] * S_t[k], 64 MB
__device__ float  g_Mu0[K_DIM];
__device__ double g_loglik;

// ---------------------------------------------------------------------------
// 0) zero the loglik accumulator (must be re-zeroed every launch: deterministic)
// ---------------------------------------------------------------------------
__global__ void init_kernel() { g_loglik = 0.0; }

// ---------------------------------------------------------------------------
// 1) Mu0[k] = mean(obs[k,:]) / 10 + 1e-5 ; also fill lams0 output region
// ---------------------------------------------------------------------------
__global__ void row_stats_kernel(const float* __restrict__ obs,
                                 float* __restrict__ out_lams0,
                                 int write_lams0) {
    int k = blockIdx.x;
    const float* row = obs + (size_t)k * N_DIM;
    float s = 0.f;
    for (int t = threadIdx.x * 4; t < N_DIM; t += blockDim.x * 4) {
        float4 v = *reinterpret_cast<const float4*>(row + t);
        s += v.x + v.y + v.z + v.w;
    }
    __shared__ float red[256];
    red[threadIdx.x] = s;
    __syncthreads();
    for (int off = 128; off > 0; off >>= 1) {
        if (threadIdx.x < off) red[threadIdx.x] += red[threadIdx.x + off];
        __syncthreads();
    }
    float mu = red[0] * (1.0f / (float)N_DIM) * 0.1f + 1e-5f;
    if (threadIdx.x == 0) g_Mu0[k] = mu;
    if (write_lams0) {
        // out_lams0 is only 4B-aligned (offset +1 float into d_out) -> scalar stores
        float* dst = out_lams0 + (size_t)k * N_DIM;
        for (int t = threadIdx.x; t < N_DIM; t += blockDim.x) dst[t] = mu;
    }
}

// ---------------------------------------------------------------------------
// 2) Chunked exponential scan with halo.
//    S_seq[0]=0 ; S_seq[t] = decay*(S_seq[t-1] + obs[:,t-1])
//    G[t][k] = Beta[k] * S_seq[t][k]
//    decay <= e^-1, so a 64-step warm-up halo makes chunks independent to ~1e-28.
// ---------------------------------------------------------------------------
__global__ void scan_kernel(const float* __restrict__ obs,
                            const float* __restrict__ Beta) {
    int id    = blockIdx.x * blockDim.x + threadIdx.x;
    int k     = id & (K_DIM - 1);
    int chunk = id >> 10;                 // log2(K_DIM) = 10
    int t0    = chunk * SCAN_C;

    float beta = Beta[k];
    float dec  = expf(-beta);
    const float* row = obs + (size_t)k * N_DIM;

    int tstart = t0 - SCAN_H;
    if (tstart < 0) tstart = 0;

    float S = 0.f;
    int t = tstart;
    // warm-up halo
    for (; t < t0; ++t) S = dec * (S + row[t]);
    // emit range
    int tend = t0 + SCAN_C;
    for (; t < tend; ++t) {
        g_G[(size_t)t * K_DIM + k] = beta * S;   // coalesced: consecutive k per warp
        S = dec * (S + row[t]);
    }
}

// ---------------------------------------------------------------------------
// 3) Fused GEMM + epilogue.
//    C[t][ko] = sum_j G[t][j] * Alpha[ko][j]   (NT gemm, both K-major)
//    lam1 = softplus(C), lam1[:,0]=0, write lam1[ko][t],
//    accumulate loglik = sum( obs*log(mu+lam1+1e-5) - mu - lam1 ).
//    128x128 block tile, BK=16, 8x8 per-thread register tile, 256 threads.
// ---------------------------------------------------------------------------
#define BM 128
#define BN 128
#define BK 16
#define TM 8
#define TN 8

__global__ __launch_bounds__(256, 2)
void gemm_epilogue_kernel(const float* __restrict__ Alpha,
                          const float* __restrict__ obs,
                          float* __restrict__ out_lam1,
                          int do_write) {
    __shared__ float As[BK][BM + 4];   // As[j][t]  (A transposed tile)
    __shared__ float Bs[BK][BN + 4];   // Bs[j][ko]
    __shared__ float red[256];

    const int t0  = blockIdx.y * BM;   // t-tile
    const int ko0 = blockIdx.x * BN;   // ko-tile (8 tiles -> consecutive blocks share G panel in L2)
    const int tid = threadIdx.x;

    float acc[TM][TN] = {};

    const int lrow = tid >> 2;          // 0..63
    const int lcol = (tid & 3) * 4;     // 0,4,8,12

    for (int j0 = 0; j0 < K_DIM; j0 += BK) {
        #pragma unroll
        for (int rr = 0; rr < 2; ++rr) {
            int r = lrow + rr * 64;
            float4 v = *reinterpret_cast<const float4*>(
                &g_G[(size_t)(t0 + r) * K_DIM + j0 + lcol]);
            As[lcol + 0][r] = v.x; As[lcol + 1][r] = v.y;
            As[lcol + 2][r] = v.z; As[lcol + 3][r] = v.w;
        }
        #pragma unroll
        for (int rr = 0; rr < 2; ++rr) {
            int r = lrow + rr * 64;
            float4 v = *reinterpret_cast<const float4*>(
                &Alpha[(size_t)(ko0 + r) * K_DIM + j0 + lcol]);
            Bs[lcol + 0][r] = v.x; Bs[lcol + 1][r] = v.y;
            Bs[lcol + 2][r] = v.z; Bs[lcol + 3][r] = v.w;
        }
        __syncthreads();

        const int ty = tid >> 4, tx = tid & 15;
        #pragma unroll
        for (int j = 0; j < BK; ++j) {
            float a[TM], b[TN];
            #pragma unroll
            for (int i = 0; i < TM; ++i) a[i] = As[j][ty * TM + i];
            #pragma unroll
            for (int l = 0; l < TN; ++l) b[l] = Bs[j][tx * TN + l];
            #pragma unroll
            for (int i = 0; i < TM; ++i)
                #pragma unroll
                for (int l = 0; l < TN; ++l)
                    acc[i][l] += a[i] * b[l];
        }
        __syncthreads();
    }

    // ---- epilogue ----
    const int ty = tid >> 4, tx = tid & 15;
    float lsum = 0.f;
    #pragma unroll
    for (int l = 0; l < TN; ++l) {
        const int ko = ko0 + tx * TN + l;
        const float mu = g_Mu0[ko];
        const size_t rowbase = (size_t)ko * N_DIM;
        #pragma unroll
        for (int i = 0; i < TM; ++i) {
            const int t = t0 + ty * TM + i;
            float x = acc[i][l];
            float lam1 = log1pf(expf(x));       // x >= 0, <= ~40 here: no overflow
            if (t == 0) lam1 = 0.f;             // t=0 branch of reference
            float o = obs[rowbase + t];
            lsum += o * logf(mu + lam1 + 1e-5f) - mu - lam1;
            if (do_write) out_lam1[rowbase + t] = lam1;  // 4B-aligned region: scalar store
        }
    }

    red[tid] = lsum;
    __syncthreads();
    for (int off = 128; off > 0; off >>= 1) {
        if (tid < off) red[tid] += red[tid + off];
        __syncthreads();
    }
    if (tid == 0) atomicAdd(&g_loglik, (double)red[0]);
}

// ---------------------------------------------------------------------------
// 4) write the scalar
// ---------------------------------------------------------------------------
__global__ void finalize_kernel(float* __restrict__ out) {
    out[0] = (float)g_loglik;
}

// ---------------------------------------------------------------------------
extern "C" void kernel_launch(void* const* d_in, const int* in_sizes, int n_in,
                              void* d_out, int out_size) {
    // Identify inputs by size (robust to ordering): obs [K*N], Beta [K], Alpha [K*K]
    const float* obs = nullptr;
    const float* Beta = nullptr;
    const float* Alpha = nullptr;
    for (int i = 0; i < n_in; ++i) {
        if (in_sizes[i] == K_DIM) Beta = (const float*)d_in[i];
        else if (in_sizes[i] == K_DIM * K_DIM) Alpha = (const float*)d_in[i];
        else if ((size_t)in_sizes[i] == (size_t)K_DIM * N_DIM) obs = (const float*)d_in[i];
    }

    float* out = (float*)d_out;
    // expected layout: [loglik(1), lams0(K*N), lam1(K*N)]
    const long long full_sz = 1LL + 2LL * K_DIM * N_DIM;
    int full = ((long long)out_size >= full_sz) ? 1 : 0;
    float* out_lams0 = out + 1;
    float* out_lam1  = out + 1 + (size_t)K_DIM * N_DIM;

    init_kernel<<<1, 1>>>();
    row_stats_kernel<<<K_DIM, 256>>>(obs, out_lams0, full);
    scan_kernel<<<(N_DIM / SCAN_C) * K_DIM / 256, 256>>>(obs, Beta);
    dim3 grid(K_DIM / BN, N_DIM / BM);   // x = ko tiles (8), y = t tiles (128)
    gemm_epilogue_kernel<<<grid, 256>>>(Alpha, obs, out_lam1, full);
    finalize_kernel<<<1, 1>>>(out);
}

// round 3
// speedup vs baseline: 4.3383x; 4.3383x over previous
#include <cuda_runtime.h>
#include <cuda_bf16.h>
#include <math.h>
#include <stdint.h>

#define K_DIM 1024
#define N_DIM 16384

// ---------------------------------------------------------------------------
// Scratch (static device globals — no dynamic allocation allowed)
// ---------------------------------------------------------------------------
__device__ __nv_bfloat16 g_Gb[(size_t)N_DIM * K_DIM];   // G[t][k] bf16, 32 MB
__device__ __nv_bfloat16 g_Ab[(size_t)K_DIM * K_DIM];   // Alpha bf16, 2 MB
__device__ float  g_Mu0[K_DIM];
__device__ double g_loglik;

// ---------------------------------------------------------------------------
// PTX helpers (baseline sm_80+ features only — no tcgen05 on this toolchain)
// ---------------------------------------------------------------------------
__device__ __forceinline__ uint32_t smem_u32(const void* p) {
    uint32_t a;
    asm("{ .reg .u64 t; cvta.to.shared.u64 t, %1; cvt.u32.u64 %0, t; }"
        : "=r"(a) : "l"(p));
    return a;
}
__device__ __forceinline__ void cp16(uint32_t dst, const void* src) {
    asm volatile("cp.async.cg.shared.global [%0], [%1], 16;"
                 :: "r"(dst), "l"(src) : "memory");
}
#define CP_COMMIT() asm volatile("cp.async.commit_group;" ::: "memory")
#define CP_WAIT(n)  asm volatile("cp.async.wait_group %0;" :: "n"(n) : "memory")

__device__ __forceinline__ void ldsm4(uint32_t* r, uint32_t addr) {
    asm volatile("ldmatrix.sync.aligned.m8n8.x4.shared.b16 {%0,%1,%2,%3}, [%4];"
                 : "=r"(r[0]), "=r"(r[1]), "=r"(r[2]), "=r"(r[3]) : "r"(addr));
}
__device__ __forceinline__ void mma16816(float* c, const uint32_t* a,
                                         uint32_t b0, uint32_t b1) {
    asm volatile(
        "mma.sync.aligned.m16n8k16.row.col.f32.bf16.bf16.f32 "
        "{%0,%1,%2,%3}, {%4,%5,%6,%7}, {%8,%9}, {%0,%1,%2,%3};"
        : "+f"(c[0]), "+f"(c[1]), "+f"(c[2]), "+f"(c[3])
        : "r"(a[0]), "r"(a[1]), "r"(a[2]), "r"(a[3]), "r"(b0), "r"(b1));
}

// ---------------------------------------------------------------------------
__global__ void init_kernel() { g_loglik = 0.0; }

// Alpha fp32 -> bf16
__global__ void conv_alpha_kernel(const float* __restrict__ A) {
    size_t i = ((size_t)blockIdx.x * blockDim.x + threadIdx.x) * 4;
    float4 v = *reinterpret_cast<const float4*>(A + i);
    *reinterpret_cast<__nv_bfloat162*>(&g_Ab[i])     = __floats2bfloat162_rn(v.x, v.y);
    *reinterpret_cast<__nv_bfloat162*>(&g_Ab[i + 2]) = __floats2bfloat162_rn(v.z, v.w);
}

// Mu0[k] = mean(obs[k,:])/10 + 1e-5 ; fill lams0 output region
__global__ void row_stats_kernel(const float* __restrict__ obs,
                                 float* __restrict__ out_lams0, int write_lams0) {
    int k = blockIdx.x;
    const float* row = obs + (size_t)k * N_DIM;
    float s = 0.f;
    for (int t = threadIdx.x * 4; t < N_DIM; t += blockDim.x * 4) {
        float4 v = *reinterpret_cast<const float4*>(row + t);
        s += v.x + v.y + v.z + v.w;
    }
    __shared__ float red[256];
    red[threadIdx.x] = s;
    __syncthreads();
    for (int off = 128; off > 0; off >>= 1) {
        if (threadIdx.x < off) red[threadIdx.x] += red[threadIdx.x + off];
        __syncthreads();
    }
    float mu = red[0] * (1.0f / (float)N_DIM) * 0.1f + 1e-5f;
    if (threadIdx.x == 0) g_Mu0[k] = mu;
    if (write_lams0) {
        float* dst = out_lams0 + (size_t)k * N_DIM;   // 4B-aligned only
        for (int t = threadIdx.x; t < N_DIM; t += blockDim.x) dst[t] = mu;
    }
}

// ---------------------------------------------------------------------------
// Fused transpose + exponential scan with 64-step halo (decay <= e^-1 =>
// halo truncation error ~ e^-64, invisible). Coalesced loads, conflict-free
// SMEM (pad 321), one warp runs 32 serial scans, coalesced bf16 G writes.
// ---------------------------------------------------------------------------
__global__ __launch_bounds__(256)
void scan_kernel(const float* __restrict__ obs, const float* __restrict__ Beta) {
    __shared__ float tile[32][321];
    const int k0 = blockIdx.y * 32;
    const int t0 = blockIdx.x * 256;
    const int tid = threadIdx.x;
    const int lane = tid & 31;
    const int tstart = t0 - 64;

    int rbase = (tid >> 5) * 4;
    #pragma unroll
    for (int r = 0; r < 4; ++r) {
        const float* src = obs + (size_t)(k0 + rbase + r) * N_DIM;
        #pragma unroll
        for (int i = 0; i < 10; ++i) {
            int col = lane + i * 32;
            int t = tstart + col;
            tile[rbase + r][col] = (t >= 0) ? src[t] : 0.f;
        }
    }
    __syncthreads();

    if (tid < 32) {
        int k = k0 + tid;
        float beta = Beta[k];
        float dec = __expf(-beta);
        float S = 0.f;
        #pragma unroll 8
        for (int i = 0; i < 64; ++i) S = dec * (S + tile[tid][i]);
        #pragma unroll 4
        for (int i = 0; i < 256; ++i) {
            g_Gb[(size_t)(t0 + i) * K_DIM + tid + k0] = __float2bfloat16(beta * S);
            S = dec * (S + tile[tid][64 + i]);
        }
        (void)k;
    }
}

// ---------------------------------------------------------------------------
// bf16 tensor-core GEMM (mma.sync m16n8k16) + fused epilogue.
// C[t][ko] = sum_j G[t][j]*Alpha[ko][j]; lam1=softplus(C); lam1[:,0]=0;
// loglik += sum(obs*log(mu+lam1+1e-5) - mu - lam1); write lam1.
//
// CTA tile 128(t) x 128(ko), BK=32, 4-stage cp.async pipeline.
// 8 warps: wm = wid&1 (2 m-warps of 64), wn = wid>>1 (4 n-warps of 32).
// SMEM tile rows padded to 40 bf16 (80B): row stride = 20 words -> each
// ldmatrix 8x8 phase hits 8 disjoint bank quads (conflict-free).
// ---------------------------------------------------------------------------
#define STAGES 4
#define TILE_B 10240              // 128 rows * 80 bytes
#define STAGE_B (2 * TILE_B)      // A tile + B tile
#define GEMM_SMEM (STAGES * STAGE_B)   // 81920

__global__ __launch_bounds__(256)
void gemm_ep_kernel(const float* __restrict__ obs,
                    float* __restrict__ out_lam1, int do_write) {
    extern __shared__ char smem[];
    const uint32_t sb = smem_u32(smem);
    const int tid = threadIdx.x;
    const int wid = tid >> 5;
    const int lane = tid & 31;
    const int wm = wid & 1;
    const int wn = wid >> 1;
    const int ko0 = blockIdx.x * 128;
    const int t0  = blockIdx.y * 128;

    const int lrow = tid >> 2;        // 0..63
    const int lch  = tid & 3;         // 0..3

    // issue one stage of loads (A: G tile, B: Alpha tile), always commit
    auto load_stage = [&](int s, int j0) {
        if (j0 < K_DIM) {
            uint32_t abase = sb + s * STAGE_B;
            uint32_t bbase = abase + TILE_B;
            #pragma unroll
            for (int p = 0; p < 2; ++p) {
                int row = lrow + p * 64;
                uint32_t doff = row * 80 + lch * 16;
                cp16(abase + doff, g_Gb + (size_t)(t0 + row) * K_DIM + j0 + lch * 8);
                cp16(bbase + doff, g_Ab + (size_t)(ko0 + row) * K_DIM + j0 + lch * 8);
            }
        }
        CP_COMMIT();
    };

    load_stage(0, 0);
    load_stage(1, 32);
    load_stage(2, 64);

    float acc[4][4][4];
    #pragma unroll
    for (int i = 0; i < 4; ++i)
        #pragma unroll
        for (int j = 0; j < 4; ++j)
            #pragma unroll
            for (int e = 0; e < 4; ++e) acc[i][j][e] = 0.f;

    const uint32_t a_lrow = (lane & 15);
    const uint32_t a_lhalf = (lane >> 4) * 16;

    #pragma unroll 1
    for (int it = 0; it < 32; ++it) {
        CP_WAIT(2);            // committed >= it+3 -> groups <= it complete
        __syncthreads();       // data visible to all; gates stage reuse
        load_stage((it + 3) & 3, (it + 3) * 32);

        uint32_t abase = sb + (it & 3) * STAGE_B;
        uint32_t bbase = abase + TILE_B;
        #pragma unroll
        for (int kk = 0; kk < 2; ++kk) {
            uint32_t a[4][4], b[2][4];
            #pragma unroll
            for (int mi = 0; mi < 4; ++mi)
                ldsm4(a[mi], abase + (wm * 64 + mi * 16 + a_lrow) * 80
                                   + a_lhalf + kk * 32);
            #pragma unroll
            for (int ng = 0; ng < 2; ++ng)
                ldsm4(b[ng], bbase + (wn * 32 + ng * 16 + a_lrow) * 80
                                   + a_lhalf + kk * 32);
            #pragma unroll
            for (int mi = 0; mi < 4; ++mi)
                #pragma unroll
                for (int ni = 0; ni < 4; ++ni)
                    mma16816(acc[mi][ni], a[mi],
                             b[ni >> 1][ni & 1], b[ni >> 1][2 + (ni & 1)]);
        }
    }

    // ---- fused epilogue straight from mma fragments ----
    float lsum = 0.f;
    #pragma unroll
    for (int mi = 0; mi < 4; ++mi) {
        #pragma unroll
        for (int ni = 0; ni < 4; ++ni) {
            const int tb = t0 + wm * 64 + mi * 16 + (lane >> 2);
            const int kb = ko0 + wn * 32 + ni * 8 + (lane & 3) * 2;
            #pragma unroll
            for (int e = 0; e < 4; ++e) {
                const int t  = tb + (e >> 1) * 8;
                const int ko = kb + (e & 1);
                float x = acc[mi][ni][e];
                float lam1 = (x > 20.f) ? x : __logf(1.f + __expf(x));
                if (t == 0) lam1 = 0.f;
                float mu = g_Mu0[ko];
                float o = __ldg(obs + (size_t)ko * N_DIM + t);
                lsum += o * __logf(mu + lam1 + 1e-5f) - mu - lam1;
                if (do_write) out_lam1[(size_t)ko * N_DIM + t] = lam1;
            }
        }
    }

    __syncthreads();                       // all smem reads done -> reuse as red
    float* red = reinterpret_cast<float*>(smem);
    red[tid] = lsum;
    __syncthreads();
    for (int off = 128; off > 0; off >>= 1) {
        if (tid < off) red[tid] += red[tid + off];
        __syncthreads();
    }
    if (tid == 0) atomicAdd(&g_loglik, (double)red[0]);
}

__global__ void finalize_kernel(float* __restrict__ out) {
    out[0] = (float)g_loglik;
}

// ---------------------------------------------------------------------------
extern "C" void kernel_launch(void* const* d_in, const int* in_sizes, int n_in,
                              void* d_out, int out_size) {
    const float *obs = nullptr, *Beta = nullptr, *Alpha = nullptr;
    for (int i = 0; i < n_in; ++i) {
        if (in_sizes[i] == K_DIM) Beta = (const float*)d_in[i];
        else if (in_sizes[i] == K_DIM * K_DIM) Alpha = (const float*)d_in[i];
        else if ((size_t)in_sizes[i] == (size_t)K_DIM * N_DIM) obs = (const float*)d_in[i];
    }
    float* out = (float*)d_out;
    const long long full_sz = 1LL + 2LL * K_DIM * N_DIM;
    int full = ((long long)out_size >= full_sz) ? 1 : 0;
    float* out_lams0 = out + 1;
    float* out_lam1  = out + 1 + (size_t)K_DIM * N_DIM;

    static int smem_set = 0;
    if (!smem_set) {
        cudaFuncSetAttribute(gemm_ep_kernel,
                             cudaFuncAttributeMaxDynamicSharedMemorySize, GEMM_SMEM);
        smem_set = 1;
    }

    init_kernel<<<1, 1>>>();
    conv_alpha_kernel<<<(K_DIM * K_DIM) / (256 * 4), 256>>>(Alpha);
    row_stats_kernel<<<K_DIM, 256>>>(obs, out_lams0, full);
    dim3 sgrid(N_DIM / 256, K_DIM / 32);
    scan_kernel<<<sgrid, 256>>>(obs, Beta);
    dim3 ggrid(K_DIM / 128, N_DIM / 128);
    gemm_ep_kernel<<<ggrid, 256, GEMM_SMEM>>>(obs, out_lam1, full);
    finalize_kernel<<<1, 1>>>(out);
}